// round 6
// baseline (speedup 1.0000x reference)
#include <cuda_runtime.h>
#include <math.h>

#define BB 2
#define TT 2048
#define CC 1024
#define HH 16
#define DD 64
#define MM (BB*TT)      // 4096
#define QTILES (TT/64)  // 32

// Scratch (device globals: allocation-free, graph-capture safe)
__device__ float g_Q[BB*HH*TT*DD];
__device__ float g_K[BB*HH*TT*DD];
__device__ float g_V[BB*HH*TT*DD];
__device__ float g_Y[BB*HH*TT*DD];
__device__ float g_part[BB*HH*QTILES*2];  // per (bh, qtile) partial (sum, sumsq)
__device__ float g_norm[BB*HH*2];         // (mu, rinv) per group

// ---------------------------------------------------------------------------
// Projection GEMM: Out[b,h,t,d] = scale * sum_k x[b,t,k] * W[h*64+d, k]
// (torch Linear: y = x @ W.T ; both operands K-contiguous => NT GEMM)
// Tile 64x64, BK=16, 256 threads, 4x4 micro-tile per thread.
// which: 0 -> g_Q, 1 -> g_K, 2 -> g_V
// ---------------------------------------------------------------------------
__global__ void proj_kernel(const float* __restrict__ A, const float* __restrict__ W,
                            int which, float scale) {
    __shared__ float As[16][64];
    __shared__ float Bs[16][64];
    float* Out = (which == 0) ? g_Q : (which == 1) ? g_K : g_V;

    int tid = threadIdx.x;
    int m0 = blockIdx.x * 64, n0 = blockIdx.y * 64;
    int tr = tid >> 4, tc = tid & 15;      // 16x16 thread grid
    int lr = tid >> 2, lk = (tid & 3) << 2; // loader: row 0..63, k-offset {0,4,8,12}

    const float* Ap = A + (size_t)(m0 + lr) * CC + lk;
    const float* Bp = W + (size_t)(n0 + lr) * CC + lk;

    float acc[4][4] = {};

    for (int k0 = 0; k0 < CC; k0 += 16) {
        float4 av = *(const float4*)(Ap + k0);
        float4 bv = *(const float4*)(Bp + k0);
        As[lk+0][lr]=av.x; As[lk+1][lr]=av.y; As[lk+2][lr]=av.z; As[lk+3][lr]=av.w;
        Bs[lk+0][lr]=bv.x; Bs[lk+1][lr]=bv.y; Bs[lk+2][lr]=bv.z; Bs[lk+3][lr]=bv.w;
        __syncthreads();
        #pragma unroll
        for (int kk = 0; kk < 16; kk++) {
            float a[4], b[4];
            #pragma unroll
            for (int i = 0; i < 4; i++) a[i] = As[kk][tr*4+i];
            #pragma unroll
            for (int j = 0; j < 4; j++) b[j] = Bs[kk][tc*4+j];
            #pragma unroll
            for (int i = 0; i < 4; i++)
                #pragma unroll
                for (int j = 0; j < 4; j++)
                    acc[i][j] = fmaf(a[i], b[j], acc[i][j]);
        }
        __syncthreads();
    }

    // scatter to (B,H,T,D)
    #pragma unroll
    for (int i = 0; i < 4; i++) {
        int m = m0 + tr*4 + i;
        int b = m >> 11;            // /T
        int t = m & (TT - 1);
        #pragma unroll
        for (int j = 0; j < 4; j++) {
            int n = n0 + tc*4 + j;
            int h = n >> 6, d = n & 63;
            Out[((size_t)(b*HH + h)*TT + t)*DD + d] = acc[i][j] * scale;
        }
    }
}

// ---------------------------------------------------------------------------
// Retention: per CTA = one (bh, 64-row query tile). Streams 64-row KV tiles.
// Decay mask gamma^(i-j) factorized per off-diagonal tile:
//   gamma^(i-j) = [gamma^(ri + dist - 63)] (row, folded into S) *
//                 [gamma^(63 - rj)]        (col, folded into K at load)
// Diagonal tile handled elementwise (exact causal mask).
// Outputs pre-GroupNorm y (B,H,T,D) + deterministic partial stats.
// NOTE: full 64x64 tile loads = 4 column-chunks of float4 per thread.
// ---------------------------------------------------------------------------
__global__ void retention_kernel() {
    extern __shared__ float sm[];
    float* Qs = sm;           // [d][i]  d*64+i
    float* Ks = sm + 4096;    // [d][j]  d*64+j   (col decay folded in)
    float* Vs = sm + 8192;    // [j][d]  j*64+d
    float* Ss = sm + 12288;   // [j][i]  j*65+i   (padded vs bank conflicts)

    int tid = threadIdx.x;
    int qt = blockIdx.x, bh = blockIdx.y;
    int h = bh & (HH - 1);
    size_t base = (size_t)bh * TT * DD;
    int i0 = qt * 64;

    float gamma = 1.0f - exp2f(-5.0f - 0.5f * (float)h);
    float lg = log2f(gamma);

    int tr = tid >> 4, tc = tid & 15;
    int lr = tid >> 2, lk = (tid & 3) << 2;

    // load Q tile (transposed to [d][i]) — 4 chunks cover all 64 columns
    #pragma unroll
    for (int cch = 0; cch < 4; cch++) {
        int col = lk + cch*16;
        float4 q = *(const float4*)(g_Q + base + (size_t)(i0 + lr)*DD + col);
        Qs[(col+0)*64+lr]=q.x; Qs[(col+1)*64+lr]=q.y;
        Qs[(col+2)*64+lr]=q.z; Qs[(col+3)*64+lr]=q.w;
    }

    float acc[4][4] = {};

    for (int j0 = 0; j0 <= i0; j0 += 64) {
        int dist = i0 - j0;
        bool diag = (dist == 0);

        float cc = diag ? 1.0f : exp2f((float)(63 - lr) * lg);
        #pragma unroll
        for (int cch = 0; cch < 4; cch++) {
            int col = lk + cch*16;
            float4 kv = *(const float4*)(g_K + base + (size_t)(j0 + lr)*DD + col);
            Ks[(col+0)*64+lr]=kv.x*cc; Ks[(col+1)*64+lr]=kv.y*cc;
            Ks[(col+2)*64+lr]=kv.z*cc; Ks[(col+3)*64+lr]=kv.w*cc;
            float4 vv = *(const float4*)(g_V + base + (size_t)(j0 + lr)*DD + col);
            *(float4*)(Vs + lr*64 + col) = vv;
        }
        __syncthreads();

        // S = Q K^T (contraction over d)
        float s[4][4] = {};
        #pragma unroll
        for (int d = 0; d < 64; d++) {
            float a[4], b[4];
            #pragma unroll
            for (int i = 0; i < 4; i++) a[i] = Qs[d*64 + tr*4 + i];
            #pragma unroll
            for (int j = 0; j < 4; j++) b[j] = Ks[d*64 + tc*4 + j];
            #pragma unroll
            for (int i = 0; i < 4; i++)
                #pragma unroll
                for (int j = 0; j < 4; j++)
                    s[i][j] = fmaf(a[i], b[j], s[i][j]);
        }

        if (!diag) {
            #pragma unroll
            for (int i = 0; i < 4; i++) {
                float rc = exp2f((float)(tr*4 + i + dist - 63) * lg);
                #pragma unroll
                for (int j = 0; j < 4; j++) s[i][j] *= rc;
            }
        } else {
            #pragma unroll
            for (int i = 0; i < 4; i++) {
                int ri = tr*4 + i;
                #pragma unroll
                for (int j = 0; j < 4; j++) {
                    int rj = tc*4 + j;
                    s[i][j] = (ri >= rj) ? s[i][j] * exp2f((float)(ri - rj) * lg) : 0.0f;
                }
            }
        }

        // stage S transposed: Ss[j][i]
        #pragma unroll
        for (int j = 0; j < 4; j++)
            #pragma unroll
            for (int i = 0; i < 4; i++)
                Ss[(tc*4 + j)*65 + tr*4 + i] = s[i][j];
        __syncthreads();

        // acc += S @ V (contraction over j)
        #pragma unroll
        for (int jj = 0; jj < 64; jj++) {
            float a[4], b[4];
            #pragma unroll
            for (int i = 0; i < 4; i++) a[i] = Ss[jj*65 + tr*4 + i];
            #pragma unroll
            for (int c = 0; c < 4; c++) b[c] = Vs[jj*64 + tc*4 + c];
            #pragma unroll
            for (int i = 0; i < 4; i++)
                #pragma unroll
                for (int c = 0; c < 4; c++)
                    acc[i][c] = fmaf(a[i], b[c], acc[i][c]);
        }
        __syncthreads();
    }

    // write y + local GroupNorm partial stats
    float lsum = 0.0f, lsq = 0.0f;
    #pragma unroll
    for (int i = 0; i < 4; i++) {
        float4 v4;
        float* pv = (float*)&v4;
        #pragma unroll
        for (int c = 0; c < 4; c++) {
            float v = acc[i][c];
            pv[c] = v; lsum += v; lsq += v*v;
        }
        *(float4*)(g_Y + base + (size_t)(i0 + tr*4 + i)*DD + tc*4) = v4;
    }

    #pragma unroll
    for (int o = 16; o > 0; o >>= 1) {
        lsum += __shfl_down_sync(0xffffffffu, lsum, o);
        lsq  += __shfl_down_sync(0xffffffffu, lsq,  o);
    }
    int wid = tid >> 5, lane = tid & 31;
    if (lane == 0) { Ss[wid] = lsum; Ss[8 + wid] = lsq; }
    __syncthreads();
    if (tid == 0) {
        float s0 = 0.0f, s1 = 0.0f;
        #pragma unroll
        for (int w = 0; w < 8; w++) { s0 += Ss[w]; s1 += Ss[8 + w]; }
        g_part[(bh*QTILES + qt)*2 + 0] = s0;   // deterministic (no atomics)
        g_part[(bh*QTILES + qt)*2 + 1] = s1;
    }
}

// ---------------------------------------------------------------------------
// GroupNorm stats: one thread per (b,h) group
// ---------------------------------------------------------------------------
__global__ void norm_stats_kernel() {
    int i = threadIdx.x;
    if (i < BB*HH) {
        float s = 0.0f, q = 0.0f;
        for (int t = 0; t < QTILES; t++) {
            s += g_part[(i*QTILES + t)*2 + 0];
            q += g_part[(i*QTILES + t)*2 + 1];
        }
        float n = (float)(TT * DD);
        float mu = s / n;
        float var = q / n - mu * mu;
        g_norm[i*2 + 0] = mu;
        g_norm[i*2 + 1] = rsqrtf(var + 1e-5f);
    }
}

// ---------------------------------------------------------------------------
// Output GEMM: out[b,t,n] = sum_k norm(y)[b,t,k] * Wo[n,k]
// GroupNorm applied on-the-fly while loading the A tile.
// ---------------------------------------------------------------------------
__global__ void out_gemm_kernel(const float* __restrict__ Wo,
                                const float* __restrict__ gnw,
                                const float* __restrict__ gnb,
                                float* __restrict__ Out) {
    __shared__ float As[16][64];
    __shared__ float Bs[16][64];

    int tid = threadIdx.x;
    int m0 = blockIdx.x * 64, n0 = blockIdx.y * 64;
    int tr = tid >> 4, tc = tid & 15;
    int lr = tid >> 2, lk = (tid & 3) << 2;

    int m = m0 + lr;
    int b = m >> 11;
    int t = m & (TT - 1);

    float acc[4][4] = {};

    for (int k0 = 0; k0 < CC; k0 += 16) {
        int k = k0 + lk;              // k..k+3 stay inside one head (64-aligned blocks)
        int hh = k >> 6, d = k & 63;
        int bh = b*HH + hh;
        float mu = g_norm[bh*2 + 0];
        float ri = g_norm[bh*2 + 1];
        float4 yv = *(const float4*)(g_Y + ((size_t)bh*TT + t)*DD + d);
        float4 wv = *(const float4*)(gnw + k);
        float4 gb = *(const float4*)(gnb + k);
        As[lk+0][lr] = (yv.x - mu)*ri*wv.x + gb.x;
        As[lk+1][lr] = (yv.y - mu)*ri*wv.y + gb.y;
        As[lk+2][lr] = (yv.z - mu)*ri*wv.z + gb.z;
        As[lk+3][lr] = (yv.w - mu)*ri*wv.w + gb.w;

        float4 wo = *(const float4*)(Wo + (size_t)(n0 + lr)*CC + k0 + lk);
        Bs[lk+0][lr]=wo.x; Bs[lk+1][lr]=wo.y; Bs[lk+2][lr]=wo.z; Bs[lk+3][lr]=wo.w;
        __syncthreads();

        #pragma unroll
        for (int kk = 0; kk < 16; kk++) {
            float a[4], bb[4];
            #pragma unroll
            for (int i = 0; i < 4; i++) a[i] = As[kk][tr*4+i];
            #pragma unroll
            for (int j = 0; j < 4; j++) bb[j] = Bs[kk][tc*4+j];
            #pragma unroll
            for (int i = 0; i < 4; i++)
                #pragma unroll
                for (int j = 0; j < 4; j++)
                    acc[i][j] = fmaf(a[i], bb[j], acc[i][j]);
        }
        __syncthreads();
    }

    #pragma unroll
    for (int i = 0; i < 4; i++) {
        size_t mm = (size_t)(m0 + tr*4 + i);
        #pragma unroll
        for (int j = 0; j < 4; j++)
            Out[mm*CC + n0 + tc*4 + j] = acc[i][j];
    }
}

// ---------------------------------------------------------------------------
extern "C" void kernel_launch(void* const* d_in, const int* in_sizes, int n_in,
                              void* d_out, int out_size) {
    const float* x   = (const float*)d_in[0];
    const float* Wq  = (const float*)d_in[1];
    const float* Wk  = (const float*)d_in[2];
    const float* Wv  = (const float*)d_in[3];
    const float* Wo  = (const float*)d_in[4];
    const float* gnw = (const float*)d_in[5];
    const float* gnb = (const float*)d_in[6];
    float* out = (float*)d_out;

    const int RET_SMEM = (12288 + 64*65) * 4;  // 65792 B
    cudaFuncSetAttribute(retention_kernel,
                         cudaFuncAttributeMaxDynamicSharedMemorySize, RET_SMEM);

    dim3 gp(MM/64, CC/64), bp(256);
    proj_kernel<<<gp, bp>>>(x, Wq, 0, 0.125f);   // 1/sqrt(64) folded into Q
    proj_kernel<<<gp, bp>>>(x, Wk, 1, 1.0f);
    proj_kernel<<<gp, bp>>>(x, Wv, 2, 1.0f);

    dim3 gr(QTILES, BB*HH);
    retention_kernel<<<gr, 256, RET_SMEM>>>();

    norm_stats_kernel<<<1, 32>>>();

    out_gemm_kernel<<<gp, bp>>>(Wo, gnw, gnb, out);
}